// round 1
// baseline (speedup 1.0000x reference)
#include <cuda_runtime.h>

// ---------------------------------------------------------------------------
// InstantNGP fused kernel, round 1: scalar fp32, smem weights + smem activations
// ---------------------------------------------------------------------------

constexpr int THREADS = 128;
constexpr unsigned TSIZE = 524288u;   // T = 2^19 (power of 2 -> mod == mask)
constexpr unsigned TMASK = TSIZE - 1u;

// shared memory float offsets (all W offsets divisible by 4 -> 16B aligned)
constexpr int OFF_W1 = 0;            // 32*64  = 2048
constexpr int OFF_B1 = 2048;         // 64
constexpr int OFF_W2 = 2112;         // 64*64  = 4096
constexpr int OFF_B2 = 6208;         // 64
constexpr int OFF_W3 = 6272;         // 64*16  = 1024
constexpr int OFF_B3 = 7296;         // 16
constexpr int OFF_W4 = 7312;         // 31*64  = 1984
constexpr int OFF_B4 = 9296;         // 64
constexpr int OFF_W5 = 9360;         // 64*64  = 4096
constexpr int OFF_B5 = 13456;        // 64
constexpr int OFF_W6 = 13520;        // 64*64  = 4096
constexpr int OFF_B6 = 17616;        // 64
constexpr int OFF_W7 = 17680;        // 64*3   = 192
constexpr int OFF_B7 = 17872;        // 3
constexpr int OFF_ACT = 17876;       // 64 * THREADS activations
constexpr int SMEM_FLOATS = OFF_ACT + 64 * THREADS;
constexpr int SMEM_BYTES  = SMEM_FLOATS * 4;

__device__ __forceinline__ void copy_smem(float* dst, const float* __restrict__ src,
                                          int n, int tid) {
    for (int i = tid; i < n; i += THREADS) dst[i] = src[i];
}

// One dense layer: h[OUT] = bias + act[K] @ W[K,OUT]
// act is this thread's private smem column (stride THREADS).
// k-loop rolled (smem addressing), j-loop fully unrolled (register accumulators).
template<int K, int OUT>
__device__ __forceinline__ void dense_layer(const float* __restrict__ sW,
                                            const float* __restrict__ sB,
                                            const float* act, float* h) {
    #pragma unroll
    for (int j = 0; j < OUT; j++) h[j] = sB[j];
    #pragma unroll 2
    for (int k = 0; k < K; k++) {
        float a = act[k * THREADS];
        const float4* wr = (const float4*)(sW + k * OUT);
        #pragma unroll
        for (int j = 0; j < OUT / 4; j++) {
            float4 w = wr[j];
            h[4*j + 0] += a * w.x;
            h[4*j + 1] += a * w.y;
            h[4*j + 2] += a * w.z;
            h[4*j + 3] += a * w.w;
        }
    }
}

__global__ __launch_bounds__(THREADS)
void ngp_fused_kernel(const float* __restrict__ pts,
                      const float* __restrict__ views,
                      const float* __restrict__ tables,
                      const float* __restrict__ W1, const float* __restrict__ b1,
                      const float* __restrict__ W2, const float* __restrict__ b2,
                      const float* __restrict__ W3, const float* __restrict__ b3,
                      const float* __restrict__ W4, const float* __restrict__ b4,
                      const float* __restrict__ W5, const float* __restrict__ b5,
                      const float* __restrict__ W6, const float* __restrict__ b6,
                      const float* __restrict__ W7, const float* __restrict__ b7,
                      float* __restrict__ out, int N) {
    extern __shared__ float s[];
    const int tid = threadIdx.x;

    copy_smem(s + OFF_W1, W1, 2048, tid);
    copy_smem(s + OFF_B1, b1, 64, tid);
    copy_smem(s + OFF_W2, W2, 4096, tid);
    copy_smem(s + OFF_B2, b2, 64, tid);
    copy_smem(s + OFF_W3, W3, 1024, tid);
    copy_smem(s + OFF_B3, b3, 16, tid);
    copy_smem(s + OFF_W4, W4, 1984, tid);
    copy_smem(s + OFF_B4, b4, 64, tid);
    copy_smem(s + OFF_W5, W5, 4096, tid);
    copy_smem(s + OFF_B5, b5, 64, tid);
    copy_smem(s + OFF_W6, W6, 4096, tid);
    copy_smem(s + OFF_B6, b6, 64, tid);
    copy_smem(s + OFF_W7, W7, 192, tid);
    copy_smem(s + OFF_B7, b7, 3, tid);
    __syncthreads();

    const int gid = blockIdx.x * THREADS + tid;
    if (gid >= N) return;

    float* act = s + OFF_ACT + tid;   // this thread's private column, stride THREADS

    // ---------------- hash grid encode: fills act[0..31] ----------------
    const float Px = pts[3 * gid + 0];
    const float Py = pts[3 * gid + 1];
    const float Pz = pts[3 * gid + 2];

    #pragma unroll 1
    for (int l = 0; l < 8; l++) {
        // res = 16 * (1024/16)^(l/7) = 16 * 2^(6l/7)
        float res = 16.0f * exp2f((float)l * (6.0f / 7.0f));
        float px = Px * res, py = Py * res, pz = Pz * res;
        float fx = floorf(px), fy = floorf(py), fz = floorf(pz);
        float wx[2], wy[2], wz[2];
        wx[1] = px - fx; wx[0] = 1.0f - wx[1];
        wy[1] = py - fy; wy[0] = 1.0f - wy[1];
        wz[1] = pz - fz; wz[0] = 1.0f - wz[1];
        unsigned ix = (unsigned)fx, iy = (unsigned)fy, iz = (unsigned)fz;
        unsigned hx[2], hy[2], hz[2];
        hx[0] = ix;                      hx[1] = ix + 1u;             // prime 1
        hy[0] = iy * 2654435761u;        hy[1] = (iy + 1u) * 2654435761u;
        hz[0] = iz * 805459861u;         hz[1] = (iz + 1u) * 805459861u;

        const float4* tab = (const float4*)tables + (size_t)l * TSIZE;
        float a0 = 0.f, a1 = 0.f, a2 = 0.f, a3 = 0.f;
        #pragma unroll
        for (int c = 0; c < 8; c++) {
            const int bx = (c >> 2) & 1, by = (c >> 1) & 1, bz = c & 1;
            unsigned idx = (hx[bx] ^ hy[by] ^ hz[bz]) & TMASK;
            float4 f = __ldg(tab + idx);
            float w = wx[bx] * wy[by] * wz[bz];
            a0 += w * f.x; a1 += w * f.y; a2 += w * f.z; a3 += w * f.w;
        }
        act[(l * 4 + 0) * THREADS] = a0;
        act[(l * 4 + 1) * THREADS] = a1;
        act[(l * 4 + 2) * THREADS] = a2;
        act[(l * 4 + 3) * THREADS] = a3;
    }

    // ---------------- density MLP: 32 -> 64 -> 64 -> 16 ----------------
    float h[64];
    dense_layer<32, 64>(s + OFF_W1, s + OFF_B1, act, h);
    #pragma unroll
    for (int j = 0; j < 64; j++) act[j * THREADS] = fmaxf(h[j], 0.0f);

    dense_layer<64, 64>(s + OFF_W2, s + OFF_B2, act, h);
    #pragma unroll
    for (int j = 0; j < 64; j++) act[j * THREADS] = fmaxf(h[j], 0.0f);

    float x16[16];
    dense_layer<64, 16>(s + OFF_W3, s + OFF_B3, act, x16);

    // density output
    out[3 * N + gid] = fmaxf(x16[0], 0.0f);

    // ---------------- build 31-dim input: x16[1:16] ++ SH16(view) ----------------
    #pragma unroll
    for (int j = 0; j < 15; j++) act[j * THREADS] = x16[j + 1];

    {
        float dx = views[3 * gid + 0];
        float dy = views[3 * gid + 1];
        float dz = views[3 * gid + 2];
        float inv = 1.0f / sqrtf(dx * dx + dy * dy + dz * dz);
        float x = dx * inv, y = dy * inv, z = dz * inv;
        float xx = x * x, yy = y * y, zz = z * z;
        act[(15 + 0)  * THREADS] = 0.28209479177387814f;
        act[(15 + 1)  * THREADS] = -0.48860251190291987f * y;
        act[(15 + 2)  * THREADS] = 0.48860251190291987f * z;
        act[(15 + 3)  * THREADS] = -0.48860251190291987f * x;
        act[(15 + 4)  * THREADS] = 1.0925484305920792f * x * y;
        act[(15 + 5)  * THREADS] = -1.0925484305920792f * y * z;
        act[(15 + 6)  * THREADS] = 0.94617469575755997f * zz - 0.31539156525252005f;
        act[(15 + 7)  * THREADS] = -1.0925484305920792f * x * z;
        act[(15 + 8)  * THREADS] = 0.54627421529603959f * (xx - yy);
        act[(15 + 9)  * THREADS] = -0.59004358992664352f * y * (3.0f * xx - yy);
        act[(15 + 10) * THREADS] = 2.8906114426405538f * x * y * z;
        act[(15 + 11) * THREADS] = -0.45704579946446572f * y * (4.0f * zz - xx - yy);
        act[(15 + 12) * THREADS] = 0.37317633259011546f * z * (2.0f * zz - 3.0f * xx - 3.0f * yy);
        act[(15 + 13) * THREADS] = -0.45704579946446572f * x * (4.0f * zz - xx - yy);
        act[(15 + 14) * THREADS] = 1.4453057213202769f * z * (xx - yy);
        act[(15 + 15) * THREADS] = -0.59004358992664352f * x * (xx - 3.0f * yy);
    }

    // ---------------- color MLP: 31 -> 64 -> 64 -> 64 -> 3 ----------------
    dense_layer<31, 64>(s + OFF_W4, s + OFF_B4, act, h);
    #pragma unroll
    for (int j = 0; j < 64; j++) act[j * THREADS] = fmaxf(h[j], 0.0f);

    dense_layer<64, 64>(s + OFF_W5, s + OFF_B5, act, h);
    #pragma unroll
    for (int j = 0; j < 64; j++) act[j * THREADS] = fmaxf(h[j], 0.0f);

    dense_layer<64, 64>(s + OFF_W6, s + OFF_B6, act, h);
    #pragma unroll
    for (int j = 0; j < 64; j++) act[j * THREADS] = fmaxf(h[j], 0.0f);

    // final 64 -> 3 (scalar weights)
    {
        const float* sW = s + OFF_W7;
        const float* sB = s + OFF_B7;
        float o0 = sB[0], o1 = sB[1], o2 = sB[2];
        #pragma unroll 4
        for (int k = 0; k < 64; k++) {
            float a = act[k * THREADS];
            o0 += a * sW[k * 3 + 0];
            o1 += a * sW[k * 3 + 1];
            o2 += a * sW[k * 3 + 2];
        }
        out[3 * gid + 0] = 1.0f / (1.0f + expf(-o0));
        out[3 * gid + 1] = 1.0f / (1.0f + expf(-o1));
        out[3 * gid + 2] = 1.0f / (1.0f + expf(-o2));
    }
}

extern "C" void kernel_launch(void* const* d_in, const int* in_sizes, int n_in,
                              void* d_out, int out_size) {
    const float* pts    = (const float*)d_in[0];
    const float* views  = (const float*)d_in[1];
    const float* tables = (const float*)d_in[2];
    const float* W1 = (const float*)d_in[3];  const float* b1 = (const float*)d_in[4];
    const float* W2 = (const float*)d_in[5];  const float* b2 = (const float*)d_in[6];
    const float* W3 = (const float*)d_in[7];  const float* b3 = (const float*)d_in[8];
    const float* W4 = (const float*)d_in[9];  const float* b4 = (const float*)d_in[10];
    const float* W5 = (const float*)d_in[11]; const float* b5 = (const float*)d_in[12];
    const float* W6 = (const float*)d_in[13]; const float* b6 = (const float*)d_in[14];
    const float* W7 = (const float*)d_in[15]; const float* b7 = (const float*)d_in[16];
    float* out = (float*)d_out;

    int N = in_sizes[0] / 3;

    cudaFuncSetAttribute(ngp_fused_kernel,
                         cudaFuncAttributeMaxDynamicSharedMemorySize, SMEM_BYTES);

    int grid = (N + THREADS - 1) / THREADS;
    ngp_fused_kernel<<<grid, THREADS, SMEM_BYTES>>>(
        pts, views, tables,
        W1, b1, W2, b2, W3, b3, W4, b4, W5, b5, W6, b6, W7, b7,
        out, N);
}

// round 3
// speedup vs baseline: 5.7800x; 5.7800x over previous
#include <cuda_runtime.h>
#include <cuda_fp16.h>
#include <cstdint>

// ---------------------------------------------------------------------------
// InstantNGP round 3: warp-level HMMA (mma.sync m16n8k16) MLP, in-register
// layer-to-layer fragment conversion, per-warp independent 32-point tiles.
// ---------------------------------------------------------------------------

constexpr int THREADS = 128;
constexpr unsigned TMASK = 524287u;      // T = 2^19 - 1
constexpr float SCALE = 1024.0f;         // density-MLP domain scale (2^10)
constexpr float INV_SCALE = 1.0f / 1024.0f;
constexpr int ST = 36;                   // stage row stride in halves (72B)

__device__ __forceinline__ void mma16816(float d[4], const uint32_t a[4],
                                         uint32_t b0, uint32_t b1) {
    asm volatile("mma.sync.aligned.m16n8k16.row.col.f32.f16.f16.f32 "
        "{%0,%1,%2,%3}, {%4,%5,%6,%7}, {%8,%9}, {%0,%1,%2,%3};"
        : "+f"(d[0]), "+f"(d[1]), "+f"(d[2]), "+f"(d[3])
        : "r"(a[0]), "r"(a[1]), "r"(a[2]), "r"(a[3]), "r"(b0), "r"(b1));
}

__device__ __forceinline__ uint32_t pack_h2(float x, float y) {
    __half2 h = __floats2half2_rn(x, y);
    return *(uint32_t*)&h;
}
__device__ __forceinline__ uint32_t pack_relu(float x, float y) {
    return pack_h2(fmaxf(x, 0.0f), fmaxf(y, 0.0f));
}

// D[m][nt][4] += A[m][kt] @ B(frag)  over KT,NT tiles; D zero-initialized here.
template<int KT, int NT>
__device__ __forceinline__ void run_layer(const uint32_t* __restrict__ F,
                                          const uint32_t A[2][4][4],
                                          float D[2][8][4], int lane) {
    #pragma unroll
    for (int m = 0; m < 2; m++)
        #pragma unroll
        for (int nt = 0; nt < NT; nt++)
            #pragma unroll
            for (int i = 0; i < 4; i++) D[m][nt][i] = 0.0f;
    #pragma unroll
    for (int kt = 0; kt < KT; kt++)
        #pragma unroll
        for (int nt = 0; nt < NT; nt++) {
            uint32_t b0 = F[((kt * NT + nt) * 2 + 0) * 32 + lane];
            uint32_t b1 = F[((kt * NT + nt) * 2 + 1) * 32 + lane];
            mma16816(D[0][nt], A[0][kt], b0, b1);
            mma16816(D[1][nt], A[1][kt], b0, b1);
        }
}

// fp32 D (+bias, relu) -> f16 A fragments of next layer, fully in registers.
template<int NT>
__device__ __forceinline__ void convert_relu(const float D[2][8][4],
                                             const float* __restrict__ bias,
                                             uint32_t A[2][4][4], int lane) {
    const int c = (lane & 3) * 2;
    #pragma unroll
    for (int kt = 0; kt < NT / 2; kt++) {
        const int j = 2 * kt;
        float b00 = bias[8 * j + c],     b01 = bias[8 * j + c + 1];
        float b10 = bias[8 * j + 8 + c], b11 = bias[8 * j + 8 + c + 1];
        #pragma unroll
        for (int m = 0; m < 2; m++) {
            A[m][kt][0] = pack_relu(D[m][j][0] + b00,     D[m][j][1] + b01);
            A[m][kt][1] = pack_relu(D[m][j][2] + b00,     D[m][j][3] + b01);
            A[m][kt][2] = pack_relu(D[m][j + 1][0] + b10, D[m][j + 1][1] + b11);
            A[m][kt][3] = pack_relu(D[m][j + 1][2] + b10, D[m][j + 1][3] + b11);
        }
    }
}

// load A fragments (KT=2 k-tiles, 32 cols) from per-warp stage
__device__ __forceinline__ void load_A2(const __half* __restrict__ st,
                                        uint32_t A[2][4][4], int lane) {
    const int r = lane >> 2, c = (lane & 3) * 2;
    #pragma unroll
    for (int m = 0; m < 2; m++)
        #pragma unroll
        for (int kt = 0; kt < 2; kt++) {
            int row = r + 16 * m, col = c + 16 * kt;
            A[m][kt][0] = *(const uint32_t*)(st + row * ST + col);
            A[m][kt][1] = *(const uint32_t*)(st + (row + 8) * ST + col);
            A[m][kt][2] = *(const uint32_t*)(st + row * ST + col + 8);
            A[m][kt][3] = *(const uint32_t*)(st + (row + 8) * ST + col + 8);
        }
}

// pre-swizzle weights into per-lane B fragments: frag[i] for
// i = ((kt*NT+nt)*2+reg)*32+lane holds half2(W[k][n], W[k+1][n])
__device__ __forceinline__ void fill_frags(uint32_t* frag, const float* __restrict__ W,
                                           int K, int Nout, int KT, int NT, int tid) {
    const int total = KT * NT * 64;
    for (int i = tid; i < total; i += THREADS) {
        int lane = i & 31, reg = (i >> 5) & 1, t = i >> 6;
        int nt = t % NT, kt = t / NT;
        int k = kt * 16 + (lane & 3) * 2 + reg * 8;
        int n = nt * 8 + (lane >> 2);
        float w0 = (k < K && n < Nout) ? W[k * Nout + n] : 0.0f;
        float w1 = (k + 1 < K && n < Nout) ? W[(k + 1) * Nout + n] : 0.0f;
        frag[i] = pack_h2(w0, w1);
    }
}

__global__ __launch_bounds__(THREADS)
void ngp_mma_kernel(const float* __restrict__ pts,
                    const float* __restrict__ views,
                    const float* __restrict__ tables,
                    const float* __restrict__ W1, const float* __restrict__ b1,
                    const float* __restrict__ W2, const float* __restrict__ b2,
                    const float* __restrict__ W3, const float* __restrict__ b3,
                    const float* __restrict__ W4, const float* __restrict__ b4,
                    const float* __restrict__ W5, const float* __restrict__ b5,
                    const float* __restrict__ W6, const float* __restrict__ b6,
                    const float* __restrict__ W7, const float* __restrict__ b7,
                    float* __restrict__ out, int N, int n_wtiles) {
    __shared__ uint32_t sF1[1024], sF2[2048], sF3[512], sF4[1024];
    __shared__ uint32_t sF5[2048], sF6[2048], sF7[256];
    __shared__ float sB1[64], sB2[64], sB3[16], sB4[64], sB5[64], sB6[64], sB7[4];
    __shared__ __half sStage[4][32 * ST];

    const int tid = threadIdx.x;
    fill_frags(sF1, W1, 32, 64, 2, 8, tid);
    fill_frags(sF2, W2, 64, 64, 4, 8, tid);
    fill_frags(sF3, W3, 64, 16, 4, 2, tid);
    fill_frags(sF4, W4, 31, 64, 2, 8, tid);
    fill_frags(sF5, W5, 64, 64, 4, 8, tid);
    fill_frags(sF6, W6, 64, 64, 4, 8, tid);
    fill_frags(sF7, W7, 64, 3, 4, 1, tid);
    if (tid < 64) {
        sB1[tid] = b1[tid] * SCALE;
        sB2[tid] = b2[tid] * SCALE;
        sB4[tid] = b4[tid];
        sB5[tid] = b5[tid];
        sB6[tid] = b6[tid];
    }
    if (tid < 16) sB3[tid] = b3[tid] * SCALE;
    if (tid < 4)  sB7[tid] = (tid < 3) ? b7[tid] : 0.0f;
    __syncthreads();

    const int lane = tid & 31, wid = tid >> 5;
    __half* st = sStage[wid];
    const int r = lane >> 2, cbase = (lane & 3) * 2;

    for (int t = blockIdx.x * 4 + wid; t < n_wtiles; t += gridDim.x * 4) {
        const int p0 = t * 32;
        const int p = p0 + lane;
        const int pp = p < N ? p : N - 1;

        const float Px = pts[3 * pp], Py = pts[3 * pp + 1], Pz = pts[3 * pp + 2];
        const float vx = views[3 * pp], vy = views[3 * pp + 1], vz = views[3 * pp + 2];

        // ---------- hash grid encode -> stage row `lane` (f16 * SCALE) ----------
        #pragma unroll 1
        for (int l = 0; l < 8; l++) {
            float res = 16.0f * exp2f((float)l * (6.0f / 7.0f));
            float px = Px * res, py = Py * res, pz = Pz * res;
            float fx = floorf(px), fy = floorf(py), fz = floorf(pz);
            float wx[2], wy[2], wz[2];
            wx[1] = px - fx; wx[0] = 1.0f - wx[1];
            wy[1] = py - fy; wy[0] = 1.0f - wy[1];
            wz[1] = pz - fz; wz[0] = 1.0f - wz[1];
            unsigned ix = (unsigned)fx, iy = (unsigned)fy, iz = (unsigned)fz;
            unsigned hx[2], hy[2], hz[2];
            hx[0] = ix;               hx[1] = ix + 1u;
            hy[0] = iy * 2654435761u; hy[1] = (iy + 1u) * 2654435761u;
            hz[0] = iz * 805459861u;  hz[1] = (iz + 1u) * 805459861u;
            const float4* tab = (const float4*)tables + (size_t)l * 524288u;
            float a0 = 0.f, a1 = 0.f, a2 = 0.f, a3 = 0.f;
            #pragma unroll
            for (int c = 0; c < 8; c++) {
                const int bx = (c >> 2) & 1, by = (c >> 1) & 1, bz = c & 1;
                unsigned idx = (hx[bx] ^ hy[by] ^ hz[bz]) & TMASK;
                float4 f = __ldg(tab + idx);
                float w = wx[bx] * wy[by] * wz[bz];
                a0 += w * f.x; a1 += w * f.y; a2 += w * f.z; a3 += w * f.w;
            }
            *(uint32_t*)(st + lane * ST + 4 * l)     = pack_h2(a0 * SCALE, a1 * SCALE);
            *(uint32_t*)(st + lane * ST + 4 * l + 2) = pack_h2(a2 * SCALE, a3 * SCALE);
        }
        __syncwarp();

        uint32_t A[2][4][4];
        float D[2][8][4];

        load_A2(st, A, lane);
        run_layer<2, 8>(sF1, A, D, lane);
        convert_relu<8>(D, sB1, A, lane);
        run_layer<4, 8>(sF2, A, D, lane);
        convert_relu<8>(D, sB2, A, lane);
        run_layer<4, 2>(sF3, A, D, lane);

        // ---------- density out + stage x16[1:16] ----------
        __syncwarp();   // all lanes done reading stage (L1) before overwrite
        #pragma unroll
        for (int m = 0; m < 2; m++) {
            const int row0 = r + 16 * m;
            if ((lane & 3) == 0) {
                float v0 = (D[m][0][0] + sB3[0]) * INV_SCALE;
                float v2 = (D[m][0][2] + sB3[0]) * INV_SCALE;
                int pt0 = p0 + row0, pt1 = p0 + row0 + 8;
                if (pt0 < N) out[3 * N + pt0] = fmaxf(v0, 0.0f);
                if (pt1 < N) out[3 * N + pt1] = fmaxf(v2, 0.0f);
            }
            #pragma unroll
            for (int nt = 0; nt < 2; nt++) {
                #pragma unroll
                for (int i = 0; i < 2; i++) {
                    int g = 8 * nt + cbase + i;
                    if (g >= 1) {
                        float bb = sB3[g];
                        st[row0 * ST + (g - 1)]       = __float2half((D[m][nt][i]     + bb) * INV_SCALE);
                        st[(row0 + 8) * ST + (g - 1)] = __float2half((D[m][nt][2 + i] + bb) * INV_SCALE);
                    }
                }
            }
        }

        // ---------- SH(view) -> stage cols 15..30, col31 = 0 ----------
        {
            float inv = rsqrtf(vx * vx + vy * vy + vz * vz);
            float x = vx * inv, y = vy * inv, z = vz * inv;
            float xx = x * x, yy = y * y, zz = z * z;
            __half* row = st + lane * ST;
            row[15] = __float2half(0.28209479177387814f);
            row[16] = __float2half(-0.48860251190291987f * y);
            row[17] = __float2half(0.48860251190291987f * z);
            row[18] = __float2half(-0.48860251190291987f * x);
            row[19] = __float2half(1.0925484305920792f * x * y);
            row[20] = __float2half(-1.0925484305920792f * y * z);
            row[21] = __float2half(0.94617469575755997f * zz - 0.31539156525252005f);
            row[22] = __float2half(-1.0925484305920792f * x * z);
            row[23] = __float2half(0.54627421529603959f * (xx - yy));
            row[24] = __float2half(-0.59004358992664352f * y * (3.0f * xx - yy));
            row[25] = __float2half(2.8906114426405538f * x * y * z);
            row[26] = __float2half(-0.45704579946446572f * y * (4.0f * zz - xx - yy));
            row[27] = __float2half(0.37317633259011546f * z * (2.0f * zz - 3.0f * xx - 3.0f * yy));
            row[28] = __float2half(-0.45704579946446572f * x * (4.0f * zz - xx - yy));
            row[29] = __float2half(1.4453057213202769f * z * (xx - yy));
            row[30] = __float2half(-0.59004358992664352f * x * (xx - 3.0f * yy));
            row[31] = __float2half(0.0f);
        }
        __syncwarp();

        load_A2(st, A, lane);
        run_layer<2, 8>(sF4, A, D, lane);
        convert_relu<8>(D, sB4, A, lane);
        run_layer<4, 8>(sF5, A, D, lane);
        convert_relu<8>(D, sB5, A, lane);
        run_layer<4, 8>(sF6, A, D, lane);
        convert_relu<8>(D, sB6, A, lane);
        run_layer<4, 1>(sF7, A, D, lane);

        // ---------- sigmoid color out (cols 0..2 of D ntile 0) ----------
        #pragma unroll
        for (int m = 0; m < 2; m++) {
            #pragma unroll
            for (int i = 0; i < 2; i++) {
                int col = cbase + i;
                if (col < 3) {
                    int pt0 = p0 + r + 16 * m, pt1 = pt0 + 8;
                    float o0 = D[m][0][i] + sB7[col];
                    float o1 = D[m][0][2 + i] + sB7[col];
                    if (pt0 < N) out[3 * pt0 + col] = 1.0f / (1.0f + __expf(-o0));
                    if (pt1 < N) out[3 * pt1 + col] = 1.0f / (1.0f + __expf(-o1));
                }
            }
        }
        __syncwarp();  // stage reuse safety for next iteration
    }
}

extern "C" void kernel_launch(void* const* d_in, const int* in_sizes, int n_in,
                              void* d_out, int out_size) {
    const float* pts    = (const float*)d_in[0];
    const float* views  = (const float*)d_in[1];
    const float* tables = (const float*)d_in[2];
    const float* W1 = (const float*)d_in[3];  const float* b1 = (const float*)d_in[4];
    const float* W2 = (const float*)d_in[5];  const float* b2 = (const float*)d_in[6];
    const float* W3 = (const float*)d_in[7];  const float* b3 = (const float*)d_in[8];
    const float* W4 = (const float*)d_in[9];  const float* b4 = (const float*)d_in[10];
    const float* W5 = (const float*)d_in[11]; const float* b5 = (const float*)d_in[12];
    const float* W6 = (const float*)d_in[13]; const float* b6 = (const float*)d_in[14];
    const float* W7 = (const float*)d_in[15]; const float* b7 = (const float*)d_in[16];
    float* out = (float*)d_out;

    int N = in_sizes[0] / 3;
    int n_wtiles = (N + 31) / 32;
    int grid = 148 * 4;                      // persistent, 4 CTAs/SM target
    int max_grid = (n_wtiles + 3) / 4;
    if (grid > max_grid) grid = max_grid;

    ngp_mma_kernel<<<grid, THREADS>>>(
        pts, views, tables,
        W1, b1, W2, b2, W3, b3, W4, b4, W5, b5, W6, b6, W7, b7,
        out, N, n_wtiles);
}